// round 12
// baseline (speedup 1.0000x reference)
#include <cuda_runtime.h>
#include <cstdint>

#define MM 4096   // B*S
#define EE 1024
#define SS 2048
#define HH 16
#define DD 64

__device__ float g_q[MM * EE];
__device__ float g_k[MM * EE];
__device__ float g_v[MM * EE];        // holds V^T: (B,H,D,S)
__device__ float g_att[MM * EE];
__device__ float g_x[MM * EE];        // tf32-rounded x
__device__ float g_w[4 * EE * EE];    // tf32-rounded Wq,Wk,Wv,Wo

__device__ __forceinline__ float ftf32(float x) {
    unsigned u;
    asm("cvt.rna.tf32.f32 %0, %1;" : "=r"(u) : "f"(x));
    return __uint_as_float(u);
}

__device__ __forceinline__ float fexp2(float x) {
    float y;
    asm("ex2.approx.ftz.f32 %0, %1;" : "=f"(y) : "f"(x));
    return y;
}

__device__ __forceinline__ void mma8(float* c, const unsigned* a, const unsigned* b) {
    asm volatile(
        "mma.sync.aligned.m16n8k8.row.col.f32.tf32.tf32.f32 "
        "{%0,%1,%2,%3}, {%4,%5,%6,%7}, {%8,%9}, {%0,%1,%2,%3};\n"
        : "+f"(c[0]), "+f"(c[1]), "+f"(c[2]), "+f"(c[3])
        : "r"(a[0]), "r"(a[1]), "r"(a[2]), "r"(a[3]), "r"(b[0]), "r"(b[1]));
}

__device__ __forceinline__ void ldsm4(unsigned& r0, unsigned& r1, unsigned& r2,
                                      unsigned& r3, unsigned addr) {
    asm volatile("ldmatrix.sync.aligned.m8n8.x4.shared.b16 {%0,%1,%2,%3}, [%4];"
                 : "=r"(r0), "=r"(r1), "=r"(r2), "=r"(r3) : "r"(addr));
}

__device__ __forceinline__ unsigned su32(const void* p) {
    return (unsigned)__cvta_generic_to_shared(p);
}

__device__ __forceinline__ void cpa16(unsigned dst, const void* src) {
    asm volatile("cp.async.cg.shared.global [%0], [%1], 16;" :: "r"(dst), "l"(src));
}
#define CP_COMMIT() asm volatile("cp.async.commit_group;")
#define CP_WAIT(N)  asm volatile("cp.async.wait_group %0;" :: "n"(N))

// ---------------------------------------------------------------------------
// tf32 pre-rounding passes
// ---------------------------------------------------------------------------
__global__ __launch_bounds__(256) void cvt_x_kernel(const float* __restrict__ src,
                                                    float* __restrict__ dst)
{
    int i = blockIdx.x * 256 + threadIdx.x;
    float4 v = ((const float4*)src)[i];
    v.x = ftf32(v.x); v.y = ftf32(v.y); v.z = ftf32(v.z); v.w = ftf32(v.w);
    ((float4*)dst)[i] = v;
}

__global__ __launch_bounds__(256) void cvt_w_kernel(
    const float* __restrict__ w0, const float* __restrict__ w1,
    const float* __restrict__ w2, const float* __restrict__ w3,
    float* __restrict__ dst)
{
    const float* src = (blockIdx.z == 0) ? w0 : (blockIdx.z == 1) ? w1
                     : (blockIdx.z == 2) ? w2 : w3;
    int i = blockIdx.x * 256 + threadIdx.x;
    float4 v = ((const float4*)src)[i];
    v.x = ftf32(v.x); v.y = ftf32(v.y); v.z = ftf32(v.z); v.w = ftf32(v.w);
    ((float4*)(dst + (size_t)blockIdx.z * EE * EE))[i] = v;
}

// ---------------------------------------------------------------------------
// GEMM: block 128x256, BK=32, 256 threads, warp tile 64x64,
// 2-stage cp.async pipeline, 2 CTAs/SM (barrier gaps covered by sibling CTA).
// PERM: 0 row-major; 1 (B,H,S,D) scaled+rounded; 2 (B,H,D,S) rounded.
// ---------------------------------------------------------------------------
#define GSTAGE 13824
#define GSMEM  (2 * GSTAGE * 4)            // 110592 bytes -> 2 CTAs/SM

__device__ __forceinline__ void gemm_issue(unsigned sA, unsigned sB,
                                           const float* Ap, const float* Bp)
{
#pragma unroll
    for (int i = 0; i < 4; i++) cpa16(sA + i * 32 * 36 * 4, Ap + (size_t)i * 32 * EE);
#pragma unroll
    for (int i = 0; i < 8; i++) cpa16(sB + i * 32 * 36 * 4, Bp + (size_t)i * 32 * EE);
    CP_COMMIT();
}

template <int PERM>
__device__ __forceinline__ void gemm_body(
    const float* __restrict__ A, const float* __restrict__ W,
    const float* __restrict__ bias, float* __restrict__ out,
    int m0, int n0, float oscale)
{
    extern __shared__ float sm[];
    const int tid = threadIdx.x;
    const int warp = tid >> 5, lane = tid & 31;
    const int wm = (warp & 1) * 64, wn = (warp >> 1) * 64;
    const int lr = lane >> 2, lc = lane & 3;
    const unsigned g = lane >> 3, r8 = lane & 7;
    const unsigned smb = su32(sm);
    const unsigned a_off = ((wm + (g & 1) * 8 + r8) * 36 + (g >> 1) * 4) * 4;
    const unsigned b_off = (4608 + (wn + (g >> 1) * 8 + r8) * 36 + (g & 1) * 4) * 4;

    float acc[4][8][4];
#pragma unroll
    for (int i = 0; i < 4; i++)
#pragma unroll
        for (int j = 0; j < 8; j++)
#pragma unroll
            for (int l = 0; l < 4; l++) acc[i][j][l] = 0.f;

    const int ar = tid >> 3;        // 0..31
    const int ac = (tid & 7) * 4;   // 0..28
    const float* Ap = A + (size_t)(m0 + ar) * EE + ac;
    const float* Bp = W + (size_t)(n0 + ar) * EE + ac;
    const unsigned sA = smb + (ar * 36 + ac) * 4;
    const unsigned sB = smb + (4608 + ar * 36 + ac) * 4;

    gemm_issue(sA, sB, Ap, Bp);
    gemm_issue(sA + GSTAGE * 4, sB + GSTAGE * 4, Ap + 32, Bp + 32);

    for (int it = 0; it < 32; it++) {
        if (it < 31) { CP_WAIT(1); } else { CP_WAIT(0); }
        __syncthreads();
        const unsigned aA = smb + (unsigned)((it & 1) * GSTAGE * 4) + a_off;
        const unsigned aB = smb + (unsigned)((it & 1) * GSTAGE * 4) + b_off;
#pragma unroll
        for (int kk = 0; kk < 4; kk++) {
            unsigned a[4][4], b[8][2];
#pragma unroll
            for (int mt = 0; mt < 4; mt++)
                ldsm4(a[mt][0], a[mt][1], a[mt][2], a[mt][3],
                      aA + (mt * 16 * 36 + kk * 8) * 4);
#pragma unroll
            for (int t = 0; t < 4; t++) {
                unsigned r0, r1, r2, r3;
                ldsm4(r0, r1, r2, r3, aB + (t * 16 * 36 + kk * 8) * 4);
                b[2 * t][0] = r0;     b[2 * t][1] = r1;
                b[2 * t + 1][0] = r2; b[2 * t + 1][1] = r3;
            }
#pragma unroll
            for (int mt = 0; mt < 4; mt++)
#pragma unroll
                for (int nt = 0; nt < 8; nt++)
                    mma8(acc[mt][nt], a[mt], b[nt]);
        }
        __syncthreads();            // reads done before refill of this buffer
        if (it + 2 < 32) {
            const unsigned st = (unsigned)((it & 1) * GSTAGE * 4);
            gemm_issue(sA + st, sB + st, Ap + (it + 2) * 32, Bp + (it + 2) * 32);
        }
    }

#pragma unroll
    for (int mt = 0; mt < 4; mt++) {
#pragma unroll
        for (int nt = 0; nt < 8; nt++) {
            int row = m0 + wm + mt * 16 + lr;
            int col = n0 + wn + nt * 8 + lc * 2;
            float bb0 = bias[col], bb1 = bias[col + 1];
            if (PERM == 1) {
                float v00 = ftf32((acc[mt][nt][0] + bb0) * oscale);
                float v01 = ftf32((acc[mt][nt][1] + bb1) * oscale);
                float v10 = ftf32((acc[mt][nt][2] + bb0) * oscale);
                float v11 = ftf32((acc[mt][nt][3] + bb1) * oscale);
                int bb = row >> 11, s = row & 2047;
                int h = col >> 6, d = col & 63;
                size_t base = (((size_t)bb * HH + h) * SS + s) * DD + d;
                out[base] = v00; out[base + 1] = v01;
                out[base + 8 * DD] = v10; out[base + 8 * DD + 1] = v11;
            } else if (PERM == 2) {
                float v00 = ftf32(acc[mt][nt][0] + bb0);
                float v01 = ftf32(acc[mt][nt][1] + bb1);
                float v10 = ftf32(acc[mt][nt][2] + bb0);
                float v11 = ftf32(acc[mt][nt][3] + bb1);
                int bb = row >> 11, s = row & 2047;
                int h = col >> 6, d = col & 63;
                size_t base = (((size_t)bb * HH + h) * DD + d) * SS + s;
                out[base] = v00;
                out[base + SS] = v01;
                out[base + 8] = v10;
                out[base + SS + 8] = v11;
            } else {
                size_t base = (size_t)row * EE + col;
                out[base] = acc[mt][nt][0] + bb0;
                out[base + 1] = acc[mt][nt][1] + bb1;
                out[base + 8 * EE] = acc[mt][nt][2] + bb0;
                out[base + 8 * EE + 1] = acc[mt][nt][3] + bb1;
            }
        }
    }
}

__global__ __launch_bounds__(256, 2) void qkv_kernel(
    const float* __restrict__ x, const float* __restrict__ w,
    const float* __restrict__ bq, const float* __restrict__ bk,
    const float* __restrict__ bv,
    float* __restrict__ q, float* __restrict__ k, float* __restrict__ v)
{
    const int m0 = blockIdx.y * 128, n0 = blockIdx.x * 256;
    if (blockIdx.z == 0)
        gemm_body<1>(x, w, bq, q, m0, n0, 0.125f * 1.44269504f);
    else if (blockIdx.z == 1)
        gemm_body<1>(x, w + EE * EE, bk, k, m0, n0, 1.f);
    else
        gemm_body<2>(x, w + 2 * EE * EE, bv, v, m0, n0, 1.f);
}

__global__ __launch_bounds__(256, 2) void proj_kernel(
    const float* __restrict__ A, const float* __restrict__ W,
    const float* __restrict__ b, float* __restrict__ o)
{
    gemm_body<0>(A, W, b, o, blockIdx.y * 128, blockIdx.x * 256, 1.f);
}

// ---------------------------------------------------------------------------
// Flash attention, causal. Q tile 256 rows, 8 warps x 32 rows (2 m-tiles),
// 256 threads. K/V tile 64 keys, double-buffered, one __syncthreads/tile.
// K/V fragments loaded once per pass feed both m-tiles (half the LDSM/FLOP).
// Smem floats: Q/P [0,17408) | K0 [17408) V0 [21760) | K1 [26112) V1 [30464)
// ---------------------------------------------------------------------------
#define KOFF 17408
#define VOFF 21760
#define ABUF (8704 * 4)

__global__ __launch_bounds__(256, 1) void attn_kernel(
    const float* __restrict__ q, const float* __restrict__ k,
    const float* __restrict__ vT, float* __restrict__ o)
{
    extern __shared__ float sm[];

    const int qt = gridDim.x - 1 - blockIdx.x;   // big tiles first
    const int q0 = qt * 256;
    const int bh = blockIdx.y;
    const int tid = threadIdx.x;
    const int warp = tid >> 5, lane = tid & 31;
    const int lr = lane >> 2, lc = lane & 3;
    const unsigned g = lane >> 3, r8 = lane & 7;
    const unsigned smb = su32(sm);

    const unsigned ks_lane0 = smb + (KOFF + ((g >> 1) * 8 + r8) * 68 + (g & 1) * 4) * 4;
    const unsigned vt_lane0 = smb + (VOFF + ((g >> 1) * 8 + r8) * 68 + (g & 1) * 4) * 4;
    const unsigned pw_lane  = smb + ((warp * 32 + (g & 1) * 8 + r8) * 68 + (g >> 1) * 4) * 4;

    const float* qb  = q  + (size_t)bh * SS * DD;
    const float* kb  = k  + (size_t)bh * SS * DD;
    const float* vTb = vT + (size_t)bh * DD * SS;

    // K/V fill roles: 256 threads, 64 rows x 64 floats each tile, 4 cpa16 ea.
    const int fr = tid & 63, fg = tid >> 6;          // row, colgrp(16 floats)
    const float* kber = kb + (size_t)fr * DD + fg * 16;
    const float* vber = vTb + (size_t)fr * SS + fg * 16;
    const unsigned kdst = smb + (KOFF + fr * 68 + fg * 16) * 4;
    const unsigned vdst = smb + (VOFF + fr * 68 + fg * 16) * 4;

    // ---- Q tile (256 rows; 1 row per thread) + tile 0 ----
    {
        const float* qsrc = qb + (size_t)(q0 + tid) * DD;
        unsigned qdsm = smb + (tid * 68) * 4;
#pragma unroll
        for (int p = 0; p < 16; p++) cpa16(qdsm + p * 16, qsrc + p * 4);
        CP_COMMIT();
#pragma unroll
        for (int p = 0; p < 4; p++) cpa16(kdst + p * 16, kber + p * 4);
#pragma unroll
        for (int p = 0; p < 4; p++) cpa16(vdst + p * 16, vber + p * 4);
        CP_COMMIT();
    }
    CP_WAIT(0);
    __syncthreads();

    // ---- hoist Q fragments for both m-tiles ----
    unsigned qf[2][8][4];
#pragma unroll
    for (int m = 0; m < 2; m++) {
        const float* qp = sm + (warp * 32 + m * 16 + lr) * 68 + lc;
#pragma unroll
        for (int kk = 0; kk < 8; kk++) {
            qf[m][kk][0] = __float_as_uint(qp[kk * 8]);
            qf[m][kk][1] = __float_as_uint(qp[8 * 68 + kk * 8]);
            qf[m][kk][2] = __float_as_uint(qp[kk * 8 + 4]);
            qf[m][kk][3] = __float_as_uint(qp[8 * 68 + kk * 8 + 4]);
        }
    }

    float m_i[2][2], l_i[2][2];
#pragma unroll
    for (int m = 0; m < 2; m++) { m_i[m][0] = m_i[m][1] = -1e30f; l_i[m][0] = l_i[m][1] = 0.f; }
    float oacc[2][8][4];
#pragma unroll
    for (int m = 0; m < 2; m++)
#pragma unroll
        for (int i = 0; i < 8; i++)
#pragma unroll
            for (int j = 0; j < 4; j++) oacc[m][i][j] = 0.f;

    const int row_base = q0 + warp * 32;     // warp's first row (32 rows)
    const int ktmax = 4 * qt + 3;

    for (int kt = 0; kt <= ktmax; kt++) {
        __syncthreads();                 // all warps done reading buffer (kt+1)&1
        if (kt < ktmax) {                // prefetch tile kt+1
            const unsigned bn = ((kt + 1) & 1) * ABUF;
            const float* kn = kber + (size_t)(kt + 1) * 64 * DD;
            const float* vn = vber + (kt + 1) * 64;
#pragma unroll
            for (int p = 0; p < 4; p++) cpa16(kdst + bn + p * 16, kn + p * 4);
#pragma unroll
            for (int p = 0; p < 4; p++) cpa16(vdst + bn + p * 16, vn + p * 4);
            CP_COMMIT();
            CP_WAIT(1);                  // tile kt complete
        } else {
            CP_WAIT(0);
        }

        const int kbase = kt * 64;
        if (kbase > row_base + 31) continue;   // fully masked for this warp

        const unsigned bo = (kt & 1) * ABUF;
        const unsigned ks_lane = ks_lane0 + bo;
        const unsigned vt_lane = vt_lane0 + bo;

        // ---- S = Q K^T for both m-tiles (K frags loaded once) ----
        float sacc[2][8][4];
#pragma unroll
        for (int m = 0; m < 2; m++)
#pragma unroll
            for (int i = 0; i < 8; i++)
#pragma unroll
                for (int j = 0; j < 4; j++) sacc[m][i][j] = 0.f;
#pragma unroll
        for (int kk = 0; kk < 8; kk++) {
#pragma unroll
            for (int t = 0; t < 4; t++) {
                unsigned b0, b1, b2, b3;
                ldsm4(b0, b1, b2, b3, ks_lane + (t * 16 * 68 + kk * 8) * 4);
                unsigned bb0[2] = { b0, b1 }, bb1[2] = { b2, b3 };
                mma8(sacc[0][2 * t], qf[0][kk], bb0);
                mma8(sacc[0][2 * t + 1], qf[0][kk], bb1);
                mma8(sacc[1][2 * t], qf[1][kk], bb0);
                mma8(sacc[1][2 * t + 1], qf[1][kk], bb1);
            }
        }

        // ---- per-m-tile mask + online softmax (ex2.approx) ----
#pragma unroll
        for (int m = 0; m < 2; m++) {
            const int mrow = row_base + m * 16;
            if (kbase + 63 > mrow) {
                const int row0 = mrow + lr;
#pragma unroll
                for (int nt = 0; nt < 8; nt++) {
                    int c0 = kbase + nt * 8 + lc * 2;
                    if (c0     > row0)     sacc[m][nt][0] = -1e30f;
                    if (c0 + 1 > row0)     sacc[m][nt][1] = -1e30f;
                    if (c0     > row0 + 8) sacc[m][nt][2] = -1e30f;
                    if (c0 + 1 > row0 + 8) sacc[m][nt][3] = -1e30f;
                }
            }

            float mx0 = -1e30f, mx1 = -1e30f;
#pragma unroll
            for (int nt = 0; nt < 8; nt++) {
                mx0 = fmaxf(mx0, fmaxf(sacc[m][nt][0], sacc[m][nt][1]));
                mx1 = fmaxf(mx1, fmaxf(sacc[m][nt][2], sacc[m][nt][3]));
            }
            mx0 = fmaxf(mx0, __shfl_xor_sync(0xffffffffu, mx0, 1));
            mx1 = fmaxf(mx1, __shfl_xor_sync(0xffffffffu, mx1, 1));
            mx0 = fmaxf(mx0, __shfl_xor_sync(0xffffffffu, mx0, 2));
            mx1 = fmaxf(mx1, __shfl_xor_sync(0xffffffffu, mx1, 2));

            float mn0 = fmaxf(m_i[m][0], mx0), mn1 = fmaxf(m_i[m][1], mx1);
            float corr0 = fexp2(m_i[m][0] - mn0), corr1 = fexp2(m_i[m][1] - mn1);
            m_i[m][0] = mn0; m_i[m][1] = mn1;

            float sum0 = 0.f, sum1 = 0.f;
#pragma unroll
            for (int nt = 0; nt < 8; nt++) {
                sacc[m][nt][0] = fexp2(sacc[m][nt][0] - mn0);
                sacc[m][nt][1] = fexp2(sacc[m][nt][1] - mn0);
                sacc[m][nt][2] = fexp2(sacc[m][nt][2] - mn1);
                sacc[m][nt][3] = fexp2(sacc[m][nt][3] - mn1);
                sum0 += sacc[m][nt][0] + sacc[m][nt][1];
                sum1 += sacc[m][nt][2] + sacc[m][nt][3];
            }
            sum0 += __shfl_xor_sync(0xffffffffu, sum0, 1);
            sum1 += __shfl_xor_sync(0xffffffffu, sum1, 1);
            sum0 += __shfl_xor_sync(0xffffffffu, sum0, 2);
            sum1 += __shfl_xor_sync(0xffffffffu, sum1, 2);
            l_i[m][0] = l_i[m][0] * corr0 + sum0;
            l_i[m][1] = l_i[m][1] * corr1 + sum1;

            if (corr0 != 1.f || corr1 != 1.f) {
#pragma unroll
                for (int dt = 0; dt < 8; dt++) {
                    oacc[m][dt][0] *= corr0; oacc[m][dt][1] *= corr0;
                    oacc[m][dt][2] *= corr1; oacc[m][dt][3] *= corr1;
                }
            }
        }

        // ---- spill P for both m-tiles to warp's 32-row Q/P slice ----
        __syncwarp();   // prior PV ldsm reads of Pw done
#pragma unroll
        for (int m = 0; m < 2; m++) {
            float* Pw = sm + (warp * 32 + m * 16) * 68;
#pragma unroll
            for (int nt = 0; nt < 8; nt++) {
                Pw[lr * 68 + nt * 8 + lc * 2]           = ftf32(sacc[m][nt][0]);
                Pw[lr * 68 + nt * 8 + lc * 2 + 1]       = ftf32(sacc[m][nt][1]);
                Pw[(lr + 8) * 68 + nt * 8 + lc * 2]     = ftf32(sacc[m][nt][2]);
                Pw[(lr + 8) * 68 + nt * 8 + lc * 2 + 1] = ftf32(sacc[m][nt][3]);
            }
        }
        __syncwarp();

        // ---- O += P @ V, V frags loaded once for both m-tiles ----
#pragma unroll
        for (int kk = 0; kk < 8; kk++) {
            unsigned pa0[4], pa1[4];
            ldsm4(pa0[0], pa0[1], pa0[2], pa0[3], pw_lane + kk * 32);
            ldsm4(pa1[0], pa1[1], pa1[2], pa1[3], pw_lane + 16 * 68 * 4 + kk * 32);
#pragma unroll
            for (int t = 0; t < 4; t++) {
                unsigned b0, b1, b2, b3;
                ldsm4(b0, b1, b2, b3, vt_lane + (t * 16 * 68 + kk * 8) * 4);
                unsigned bb0[2] = { b0, b1 }, bb1[2] = { b2, b3 };
                mma8(oacc[0][2 * t], pa0, bb0);
                mma8(oacc[0][2 * t + 1], pa0, bb1);
                mma8(oacc[1][2 * t], pa1, bb0);
                mma8(oacc[1][2 * t + 1], pa1, bb1);
            }
        }
    }

    // ---- epilogue: normalize, pre-round for proj, write (B, S, E) ----
    int bb = bh >> 4, h = bh & 15;
#pragma unroll
    for (int m = 0; m < 2; m++) {
        float inv0 = 1.f / l_i[m][0], inv1 = 1.f / l_i[m][1];
        int s0 = q0 + warp * 32 + m * 16 + lr;
#pragma unroll
        for (int dt = 0; dt < 8; dt++) {
            int d = dt * 8 + lc * 2;
            size_t i0 = ((size_t)bb * SS + s0) * EE + h * 64 + d;
            o[i0] = ftf32(oacc[m][dt][0] * inv0);
            o[i0 + 1] = ftf32(oacc[m][dt][1] * inv0);
            size_t i1 = i0 + (size_t)8 * EE;
            o[i1] = ftf32(oacc[m][dt][2] * inv1);
            o[i1 + 1] = ftf32(oacc[m][dt][3] * inv1);
        }
    }
}

// ---------------------------------------------------------------------------
extern "C" void kernel_launch(void* const* d_in, const int* in_sizes, int n_in,
                              void* d_out, int out_size)
{
    const float* x  = (const float*)d_in[0];
    const float* Wq = (const float*)d_in[1];
    const float* bq = (const float*)d_in[2];
    const float* Wk = (const float*)d_in[3];
    const float* bk = (const float*)d_in[4];
    const float* Wv = (const float*)d_in[5];
    const float* bv = (const float*)d_in[6];
    const float* Wo = (const float*)d_in[7];
    const float* bo = (const float*)d_in[8];

    void *pq, *pk, *pv, *pa, *px, *pw;
    cudaGetSymbolAddress(&pq, g_q);
    cudaGetSymbolAddress(&pk, g_k);
    cudaGetSymbolAddress(&pv, g_v);
    cudaGetSymbolAddress(&pa, g_att);
    cudaGetSymbolAddress(&px, g_x);
    cudaGetSymbolAddress(&pw, g_w);
    float* fx = (float*)px;
    float* fw = (float*)pw;

    const int attn_smem = (256 * 68 + 4 * 64 * 68) * 4;   // 139264
    cudaFuncSetAttribute(qkv_kernel, cudaFuncAttributeMaxDynamicSharedMemorySize, GSMEM);
    cudaFuncSetAttribute(proj_kernel, cudaFuncAttributeMaxDynamicSharedMemorySize, GSMEM);
    cudaFuncSetAttribute(attn_kernel, cudaFuncAttributeMaxDynamicSharedMemorySize, attn_smem);

    cvt_x_kernel<<<MM * EE / 4 / 256, 256>>>(x, fx);
    cvt_w_kernel<<<dim3(EE * EE / 4 / 256, 1, 4), 256>>>(Wq, Wk, Wv, Wo, fw);

    qkv_kernel<<<dim3(EE / 256, MM / 128, 3), 256, GSMEM>>>(
        fx, fw, bq, bk, bv, (float*)pq, (float*)pk, (float*)pv);

    attn_kernel<<<dim3(SS / 256, 2 * HH), 256, attn_smem>>>(
        (const float*)pq, (const float*)pk, (const float*)pv, (float*)pa);

    proj_kernel<<<dim3(EE / 256, MM / 128), 256, GSMEM>>>(
        (const float*)pa, fw + 3 * EE * EE, bo, (float*)d_out);
}

// round 13
// speedup vs baseline: 3.2669x; 3.2669x over previous
#include <cuda_runtime.h>
#include <cstdint>

#define MM 4096   // B*S
#define EE 1024
#define SS 2048
#define HH 16
#define DD 64

__device__ float g_q[MM * EE];
__device__ float g_k[MM * EE];
__device__ float g_v[MM * EE];        // holds V^T: (B,H,D,S)
__device__ float g_att[MM * EE];
__device__ float g_x[MM * EE];        // tf32-rounded x
__device__ float g_w[4 * EE * EE];    // tf32-rounded Wq,Wk,Wv,Wo

__device__ __forceinline__ float ftf32(float x) {
    unsigned u;
    asm("cvt.rna.tf32.f32 %0, %1;" : "=r"(u) : "f"(x));
    return __uint_as_float(u);
}

__device__ __forceinline__ float fexp2(float x) {
    float y;
    asm("ex2.approx.ftz.f32 %0, %1;" : "=f"(y) : "f"(x));
    return y;
}

__device__ __forceinline__ void mma8(float* c, const unsigned* a, const unsigned* b) {
    asm volatile(
        "mma.sync.aligned.m16n8k8.row.col.f32.tf32.tf32.f32 "
        "{%0,%1,%2,%3}, {%4,%5,%6,%7}, {%8,%9}, {%0,%1,%2,%3};\n"
        : "+f"(c[0]), "+f"(c[1]), "+f"(c[2]), "+f"(c[3])
        : "r"(a[0]), "r"(a[1]), "r"(a[2]), "r"(a[3]), "r"(b[0]), "r"(b[1]));
}

__device__ __forceinline__ void ldsm4(unsigned& r0, unsigned& r1, unsigned& r2,
                                      unsigned& r3, unsigned addr) {
    asm volatile("ldmatrix.sync.aligned.m8n8.x4.shared.b16 {%0,%1,%2,%3}, [%4];"
                 : "=r"(r0), "=r"(r1), "=r"(r2), "=r"(r3) : "r"(addr));
}

__device__ __forceinline__ unsigned su32(const void* p) {
    return (unsigned)__cvta_generic_to_shared(p);
}

__device__ __forceinline__ void cpa16(unsigned dst, const void* src) {
    asm volatile("cp.async.cg.shared.global [%0], [%1], 16;" :: "r"(dst), "l"(src));
}
#define CP_COMMIT() asm volatile("cp.async.commit_group;")
#define CP_WAIT(N)  asm volatile("cp.async.wait_group %0;" :: "n"(N))

// ---------------------------------------------------------------------------
// tf32 pre-rounding passes
// ---------------------------------------------------------------------------
__global__ __launch_bounds__(256) void cvt_x_kernel(const float* __restrict__ src,
                                                    float* __restrict__ dst)
{
    int i = blockIdx.x * 256 + threadIdx.x;
    float4 v = ((const float4*)src)[i];
    v.x = ftf32(v.x); v.y = ftf32(v.y); v.z = ftf32(v.z); v.w = ftf32(v.w);
    ((float4*)dst)[i] = v;
}

__global__ __launch_bounds__(256) void cvt_w_kernel(
    const float* __restrict__ w0, const float* __restrict__ w1,
    const float* __restrict__ w2, const float* __restrict__ w3,
    float* __restrict__ dst)
{
    const float* src = (blockIdx.z == 0) ? w0 : (blockIdx.z == 1) ? w1
                     : (blockIdx.z == 2) ? w2 : w3;
    int i = blockIdx.x * 256 + threadIdx.x;
    float4 v = ((const float4*)src)[i];
    v.x = ftf32(v.x); v.y = ftf32(v.y); v.z = ftf32(v.z); v.w = ftf32(v.w);
    ((float4*)(dst + (size_t)blockIdx.z * EE * EE))[i] = v;
}

// ---------------------------------------------------------------------------
// GEMM (measured-best R8 config): block 128x256, BK=32, 256 threads,
// warp tile 64x64, 3-stage cp.async pipeline, 1 CTA/SM.
// PERM: 0 row-major; 1 (B,H,S,D) scaled+rounded; 2 (B,H,D,S) rounded.
// ---------------------------------------------------------------------------
#define GSTAGE 13824
#define GSMEM  (3 * GSTAGE * 4)

__device__ __forceinline__ void gemm_issue(unsigned sA, unsigned sB,
                                           const float* Ap, const float* Bp)
{
#pragma unroll
    for (int i = 0; i < 4; i++) cpa16(sA + i * 32 * 36 * 4, Ap + (size_t)i * 32 * EE);
#pragma unroll
    for (int i = 0; i < 8; i++) cpa16(sB + i * 32 * 36 * 4, Bp + (size_t)i * 32 * EE);
    CP_COMMIT();
}

template <int PERM>
__device__ __forceinline__ void gemm_body(
    const float* __restrict__ A, const float* __restrict__ W,
    const float* __restrict__ bias, float* __restrict__ out,
    int m0, int n0, float oscale)
{
    extern __shared__ float sm[];
    const int tid = threadIdx.x;
    const int warp = tid >> 5, lane = tid & 31;
    const int wm = (warp & 1) * 64, wn = (warp >> 1) * 64;
    const int lr = lane >> 2, lc = lane & 3;
    const unsigned g = lane >> 3, r8 = lane & 7;
    const unsigned smb = su32(sm);
    const unsigned a_off = ((wm + (g & 1) * 8 + r8) * 36 + (g >> 1) * 4) * 4;
    const unsigned b_off = (4608 + (wn + (g >> 1) * 8 + r8) * 36 + (g & 1) * 4) * 4;

    float acc[4][8][4];
#pragma unroll
    for (int i = 0; i < 4; i++)
#pragma unroll
        for (int j = 0; j < 8; j++)
#pragma unroll
            for (int l = 0; l < 4; l++) acc[i][j][l] = 0.f;

    const int ar = tid >> 3;        // 0..31
    const int ac = (tid & 7) * 4;   // 0..28
    const float* Ap = A + (size_t)(m0 + ar) * EE + ac;
    const float* Bp = W + (size_t)(n0 + ar) * EE + ac;
    const unsigned sA = smb + (ar * 36 + ac) * 4;
    const unsigned sB = smb + (4608 + ar * 36 + ac) * 4;

    gemm_issue(sA, sB, Ap, Bp);
    gemm_issue(sA + GSTAGE * 4, sB + GSTAGE * 4, Ap + 32, Bp + 32);

    for (int it = 0; it < 32; it++) {
        CP_WAIT(1);
        __syncthreads();
        if (it + 2 < 32) {
            const int st = (it + 2) % 3;
            gemm_issue(sA + st * GSTAGE * 4, sB + st * GSTAGE * 4,
                       Ap + (it + 2) * 32, Bp + (it + 2) * 32);
        } else {
            CP_COMMIT();
        }
        const unsigned aA = smb + (unsigned)((it % 3) * GSTAGE * 4) + a_off;
        const unsigned aB = smb + (unsigned)((it % 3) * GSTAGE * 4) + b_off;
#pragma unroll
        for (int kk = 0; kk < 4; kk++) {
            unsigned a[4][4], b[8][2];
#pragma unroll
            for (int mt = 0; mt < 4; mt++)
                ldsm4(a[mt][0], a[mt][1], a[mt][2], a[mt][3],
                      aA + (mt * 16 * 36 + kk * 8) * 4);
#pragma unroll
            for (int t = 0; t < 4; t++) {
                unsigned r0, r1, r2, r3;
                ldsm4(r0, r1, r2, r3, aB + (t * 16 * 36 + kk * 8) * 4);
                b[2 * t][0] = r0;     b[2 * t][1] = r1;
                b[2 * t + 1][0] = r2; b[2 * t + 1][1] = r3;
            }
#pragma unroll
            for (int mt = 0; mt < 4; mt++)
#pragma unroll
                for (int nt = 0; nt < 8; nt++)
                    mma8(acc[mt][nt], a[mt], b[nt]);
        }
    }

#pragma unroll
    for (int mt = 0; mt < 4; mt++) {
#pragma unroll
        for (int nt = 0; nt < 8; nt++) {
            int row = m0 + wm + mt * 16 + lr;
            int col = n0 + wn + nt * 8 + lc * 2;
            float bb0 = bias[col], bb1 = bias[col + 1];
            if (PERM == 1) {
                float v00 = ftf32((acc[mt][nt][0] + bb0) * oscale);
                float v01 = ftf32((acc[mt][nt][1] + bb1) * oscale);
                float v10 = ftf32((acc[mt][nt][2] + bb0) * oscale);
                float v11 = ftf32((acc[mt][nt][3] + bb1) * oscale);
                int bb = row >> 11, s = row & 2047;
                int h = col >> 6, d = col & 63;
                size_t base = (((size_t)bb * HH + h) * SS + s) * DD + d;
                out[base] = v00; out[base + 1] = v01;
                out[base + 8 * DD] = v10; out[base + 8 * DD + 1] = v11;
            } else if (PERM == 2) {
                float v00 = ftf32(acc[mt][nt][0] + bb0);
                float v01 = ftf32(acc[mt][nt][1] + bb1);
                float v10 = ftf32(acc[mt][nt][2] + bb0);
                float v11 = ftf32(acc[mt][nt][3] + bb1);
                int bb = row >> 11, s = row & 2047;
                int h = col >> 6, d = col & 63;
                size_t base = (((size_t)bb * HH + h) * DD + d) * SS + s;
                out[base] = v00;
                out[base + SS] = v01;
                out[base + 8] = v10;
                out[base + SS + 8] = v11;
            } else {
                size_t base = (size_t)row * EE + col;
                out[base] = acc[mt][nt][0] + bb0;
                out[base + 1] = acc[mt][nt][1] + bb1;
                out[base + 8 * EE] = acc[mt][nt][2] + bb0;
                out[base + 8 * EE + 1] = acc[mt][nt][3] + bb1;
            }
        }
    }
}

__global__ __launch_bounds__(256) void qkv_kernel(
    const float* __restrict__ x, const float* __restrict__ w,
    const float* __restrict__ bq, const float* __restrict__ bk,
    const float* __restrict__ bv,
    float* __restrict__ q, float* __restrict__ k, float* __restrict__ v)
{
    const int m0 = blockIdx.y * 128, n0 = blockIdx.x * 256;
    if (blockIdx.z == 0)
        gemm_body<1>(x, w, bq, q, m0, n0, 0.125f * 1.44269504f);
    else if (blockIdx.z == 1)
        gemm_body<1>(x, w + EE * EE, bk, k, m0, n0, 1.f);
    else
        gemm_body<2>(x, w + 2 * EE * EE, bv, v, m0, n0, 1.f);
}

__global__ __launch_bounds__(256) void proj_kernel(
    const float* __restrict__ A, const float* __restrict__ W,
    const float* __restrict__ b, float* __restrict__ o)
{
    gemm_body<0>(A, W, b, o, blockIdx.y * 128, blockIdx.x * 256, 1.f);
}

// ---------------------------------------------------------------------------
// Flash attention, causal (R8 measured config). Q tile 256 rows (16 warps x
// 16 rows, 512 threads), K/V tile 64 keys, double-buffered, one barrier/tile.
// Unconditional O-rescale (removes per-row divergent branch).
// Smem floats: Q/P [0,17408) | K0 [17408) V0 [21760) | K1 [26112) V1 [30464)
// ---------------------------------------------------------------------------
#define KOFF 17408
#define VOFF 21760
#define ABUF (8704 * 4)

__global__ __launch_bounds__(512, 1) void attn_kernel(
    const float* __restrict__ q, const float* __restrict__ k,
    const float* __restrict__ vT, float* __restrict__ o)
{
    extern __shared__ float sm[];

    const int qt = gridDim.x - 1 - blockIdx.x;   // big tiles first
    const int q0 = qt * 256;
    const int bh = blockIdx.y;
    const int tid = threadIdx.x;
    const int warp = tid >> 5, lane = tid & 31;
    const int lr = lane >> 2, lc = lane & 3;
    const unsigned g = lane >> 3, r8 = lane & 7;
    const unsigned smb = su32(sm);

    const unsigned ks_lane0 = smb + (KOFF + ((g >> 1) * 8 + r8) * 68 + (g & 1) * 4) * 4;
    const unsigned vt_lane0 = smb + (VOFF + ((g >> 1) * 8 + r8) * 68 + (g & 1) * 4) * 4;
    const unsigned pw_lane  = smb + ((warp * 16 + (g & 1) * 8 + r8) * 68 + (g >> 1) * 4) * 4;

    const float* qb  = q  + (size_t)bh * SS * DD;
    const float* kb  = k  + (size_t)bh * SS * DD;
    const float* vTb = vT + (size_t)bh * DD * SS;

    const int fr = tid & 63, fg = tid >> 6;
    const float* kber = kb + (size_t)fr * DD + fg * 8;
    const float* vber = vTb + (size_t)fr * SS + fg * 8;
    const unsigned kdst = smb + (KOFF + fr * 68 + fg * 8) * 4;
    const unsigned vdst = smb + (VOFF + fr * 68 + fg * 8) * 4;

    // ---- Q tile (256 rows) + tile 0 ----
    {
        const int qr = tid & 255, qg = tid >> 8;
        const float* qsrc = qb + (size_t)(q0 + qr) * DD + qg * 32;
        unsigned qdsm = smb + (qr * 68 + qg * 32) * 4;
#pragma unroll
        for (int p = 0; p < 8; p++) cpa16(qdsm + p * 16, qsrc + p * 4);
        CP_COMMIT();
        cpa16(kdst, kber);           cpa16(kdst + 16, kber + 4);
        cpa16(vdst, vber);           cpa16(vdst + 16, vber + 4);
        CP_COMMIT();
    }
    CP_WAIT(0);
    __syncthreads();

    // ---- hoist Q fragments (own warp slice) ----
    unsigned qf[8][4];
    {
        const float* qp = sm + (warp * 16 + lr) * 68 + lc;
#pragma unroll
        for (int kk = 0; kk < 8; kk++) {
            qf[kk][0] = __float_as_uint(qp[kk * 8]);
            qf[kk][1] = __float_as_uint(qp[8 * 68 + kk * 8]);
            qf[kk][2] = __float_as_uint(qp[kk * 8 + 4]);
            qf[kk][3] = __float_as_uint(qp[8 * 68 + kk * 8 + 4]);
        }
    }

    float m_i0 = -1e30f, m_i1 = -1e30f, l0 = 0.f, l1 = 0.f;
    float oacc[8][4];
#pragma unroll
    for (int i = 0; i < 8; i++)
#pragma unroll
        for (int j = 0; j < 4; j++) oacc[i][j] = 0.f;

    const int row_base = q0 + warp * 16;
    const int ktmax = 4 * qt + 3;

    for (int kt = 0; kt <= ktmax; kt++) {
        __syncthreads();                 // all warps done reading buffer (kt+1)&1
        if (kt < ktmax) {                // prefetch tile kt+1 into buffer (kt+1)&1
            const unsigned bn = ((kt + 1) & 1) * ABUF;
            const float* kn = kber + (size_t)(kt + 1) * 64 * DD;
            const float* vn = vber + (kt + 1) * 64;
            cpa16(kdst + bn, kn);        cpa16(kdst + bn + 16, kn + 4);
            cpa16(vdst + bn, vn);        cpa16(vdst + bn + 16, vn + 4);
            CP_COMMIT();
            CP_WAIT(1);                  // tile kt complete
        } else {
            CP_WAIT(0);
        }

        if (kt * 64 > row_base + 15) continue;   // fully masked for this warp

        const unsigned bo = (kt & 1) * ABUF;
        const unsigned ks_lane = ks_lane0 + bo;
        const unsigned vt_lane = vt_lane0 + bo;

        // ---- S = Q K^T ----
        float sacc[8][4];
#pragma unroll
        for (int i = 0; i < 8; i++)
#pragma unroll
            for (int j = 0; j < 4; j++) sacc[i][j] = 0.f;
#pragma unroll
        for (int kk = 0; kk < 8; kk++) {
#pragma unroll
            for (int t = 0; t < 4; t++) {
                unsigned b0, b1, b2, b3;
                ldsm4(b0, b1, b2, b3, ks_lane + (t * 16 * 68 + kk * 8) * 4);
                unsigned bb0[2] = { b0, b1 }, bb1[2] = { b2, b3 };
                mma8(sacc[2 * t], qf[kk], bb0);
                mma8(sacc[2 * t + 1], qf[kk], bb1);
            }
        }

        // ---- causal mask (log2-domain scores) ----
        if (kt * 64 + 63 > row_base) {
            const int row0 = row_base + lr;
#pragma unroll
            for (int nt = 0; nt < 8; nt++) {
                int c0 = kt * 64 + nt * 8 + lc * 2;
                if (c0     > row0)     sacc[nt][0] = -1e30f;
                if (c0 + 1 > row0)     sacc[nt][1] = -1e30f;
                if (c0     > row0 + 8) sacc[nt][2] = -1e30f;
                if (c0 + 1 > row0 + 8) sacc[nt][3] = -1e30f;
            }
        }

        // ---- online softmax (ex2.approx) ----
        float mx0 = -1e30f, mx1 = -1e30f;
#pragma unroll
        for (int nt = 0; nt < 8; nt++) {
            mx0 = fmaxf(mx0, fmaxf(sacc[nt][0], sacc[nt][1]));
            mx1 = fmaxf(mx1, fmaxf(sacc[nt][2], sacc[nt][3]));
        }
        mx0 = fmaxf(mx0, __shfl_xor_sync(0xffffffffu, mx0, 1));
        mx1 = fmaxf(mx1, __shfl_xor_sync(0xffffffffu, mx1, 1));
        mx0 = fmaxf(mx0, __shfl_xor_sync(0xffffffffu, mx0, 2));
        mx1 = fmaxf(mx1, __shfl_xor_sync(0xffffffffu, mx1, 2));

        float mn0 = fmaxf(m_i0, mx0), mn1 = fmaxf(m_i1, mx1);
        float corr0 = fexp2(m_i0 - mn0), corr1 = fexp2(m_i1 - mn1);
        m_i0 = mn0; m_i1 = mn1;

        float sum0 = 0.f, sum1 = 0.f;
#pragma unroll
        for (int nt = 0; nt < 8; nt++) {
            sacc[nt][0] = fexp2(sacc[nt][0] - mn0);
            sacc[nt][1] = fexp2(sacc[nt][1] - mn0);
            sacc[nt][2] = fexp2(sacc[nt][2] - mn1);
            sacc[nt][3] = fexp2(sacc[nt][3] - mn1);
            sum0 += sacc[nt][0] + sacc[nt][1];
            sum1 += sacc[nt][2] + sacc[nt][3];
        }
        sum0 += __shfl_xor_sync(0xffffffffu, sum0, 1);
        sum1 += __shfl_xor_sync(0xffffffffu, sum1, 1);
        sum0 += __shfl_xor_sync(0xffffffffu, sum0, 2);
        sum1 += __shfl_xor_sync(0xffffffffu, sum1, 2);
        l0 = l0 * corr0 + sum0;
        l1 = l1 * corr1 + sum1;

        // unconditional rescale (branch was per-row divergent)
#pragma unroll
        for (int dt = 0; dt < 8; dt++) {
            oacc[dt][0] *= corr0; oacc[dt][1] *= corr0;
            oacc[dt][2] *= corr1; oacc[dt][3] *= corr1;
        }

        // ---- spill P to this warp's Q-region slice ----
        float* Pw = sm + warp * 16 * 68;
        __syncwarp();
#pragma unroll
        for (int nt = 0; nt < 8; nt++) {
            Pw[lr * 68 + nt * 8 + lc * 2]           = ftf32(sacc[nt][0]);
            Pw[lr * 68 + nt * 8 + lc * 2 + 1]       = ftf32(sacc[nt][1]);
            Pw[(lr + 8) * 68 + nt * 8 + lc * 2]     = ftf32(sacc[nt][2]);
            Pw[(lr + 8) * 68 + nt * 8 + lc * 2 + 1] = ftf32(sacc[nt][3]);
        }
        __syncwarp();

        // ---- O += P @ V ----
#pragma unroll
        for (int kk = 0; kk < 8; kk++) {
            unsigned pa[4];
            ldsm4(pa[0], pa[1], pa[2], pa[3], pw_lane + kk * 32);
#pragma unroll
            for (int t = 0; t < 4; t++) {
                unsigned b0, b1, b2, b3;
                ldsm4(b0, b1, b2, b3, vt_lane + (t * 16 * 68 + kk * 8) * 4);
                unsigned bb0[2] = { b0, b1 }, bb1[2] = { b2, b3 };
                mma8(oacc[2 * t], pa, bb0);
                mma8(oacc[2 * t + 1], pa, bb1);
            }
        }
    }

    // ---- epilogue: normalize, pre-round for proj, write (B, S, E) ----
    float inv0 = 1.f / l0, inv1 = 1.f / l1;
    int bb = bh >> 4, h = bh & 15;
    int s0 = q0 + warp * 16 + lr;
#pragma unroll
    for (int dt = 0; dt < 8; dt++) {
        int d = dt * 8 + lc * 2;
        size_t i0 = ((size_t)bb * SS + s0) * EE + h * 64 + d;
        o[i0] = ftf32(oacc[dt][0] * inv0);
        o[i0 + 1] = ftf32(oacc[dt][1] * inv0);
        size_t i1 = i0 + (size_t)8 * EE;
        o[i1] = ftf32(oacc[dt][2] * inv1);
        o[i1 + 1] = ftf32(oacc[dt][3] * inv1);
    }
}

// ---------------------------------------------------------------------------
extern "C" void kernel_launch(void* const* d_in, const int* in_sizes, int n_in,
                              void* d_out, int out_size)
{
    const float* x  = (const float*)d_in[0];
    const float* Wq = (const float*)d_in[1];
    const float* bq = (const float*)d_in[2];
    const float* Wk = (const float*)d_in[3];
    const float* bk = (const float*)d_in[4];
    const float* Wv = (const float*)d_in[5];
    const float* bv = (const float*)d_in[6];
    const float* Wo = (const float*)d_in[7];
    const float* bo = (const float*)d_in[8];

    void *pq, *pk, *pv, *pa, *px, *pw;
    cudaGetSymbolAddress(&pq, g_q);
    cudaGetSymbolAddress(&pk, g_k);
    cudaGetSymbolAddress(&pv, g_v);
    cudaGetSymbolAddress(&pa, g_att);
    cudaGetSymbolAddress(&px, g_x);
    cudaGetSymbolAddress(&pw, g_w);
    float* fx = (float*)px;
    float* fw = (float*)pw;

    const int attn_smem = (256 * 68 + 4 * 64 * 68) * 4;   // 139264
    cudaFuncSetAttribute(qkv_kernel, cudaFuncAttributeMaxDynamicSharedMemorySize, GSMEM);
    cudaFuncSetAttribute(proj_kernel, cudaFuncAttributeMaxDynamicSharedMemorySize, GSMEM);
    cudaFuncSetAttribute(attn_kernel, cudaFuncAttributeMaxDynamicSharedMemorySize, attn_smem);

    cvt_x_kernel<<<MM * EE / 4 / 256, 256>>>(x, fx);
    cvt_w_kernel<<<dim3(EE * EE / 4 / 256, 1, 4), 256>>>(Wq, Wk, Wv, Wo, fw);

    qkv_kernel<<<dim3(EE / 256, MM / 128, 3), 256, GSMEM>>>(
        fx, fw, bq, bk, bv, (float*)pq, (float*)pk, (float*)pv);

    attn_kernel<<<dim3(SS / 256, 2 * HH), 512, attn_smem>>>(
        (const float*)pq, (const float*)pk, (const float*)pv, (float*)pa);

    proj_kernel<<<dim3(EE / 256, MM / 128), 256, GSMEM>>>(
        (const float*)pa, fw + 3 * EE * EE, bo, (float*)d_out);
}

// round 16
// speedup vs baseline: 5.2329x; 1.6018x over previous
#include <cuda_runtime.h>
#include <cuda_fp16.h>
#include <cstdint>

#define MM 4096   // B*S
#define EE 1024
#define SS 2048
#define HH 16
#define DD 64

__device__ __half g_q[MM * EE];
__device__ __half g_k[MM * EE];
__device__ __half g_v[MM * EE];       // holds V^T: (B,H,D,S)
__device__ __half g_att[MM * EE];
__device__ __half g_x[MM * EE];       // fp16 x
__device__ __half g_w[4 * EE * EE];   // fp16 Wq,Wk,Wv,Wo

__device__ __forceinline__ float fexp2(float x) {
    float y;
    asm("ex2.approx.ftz.f32 %0, %1;" : "=f"(y) : "f"(x));
    return y;
}

// m16n8k16 fp16 MMA, fp32 accumulate
__device__ __forceinline__ void mma16(float* c, const unsigned* a, const unsigned* b) {
    asm volatile(
        "mma.sync.aligned.m16n8k16.row.col.f32.f16.f16.f32 "
        "{%0,%1,%2,%3}, {%4,%5,%6,%7}, {%8,%9}, {%0,%1,%2,%3};\n"
        : "+f"(c[0]), "+f"(c[1]), "+f"(c[2]), "+f"(c[3])
        : "r"(a[0]), "r"(a[1]), "r"(a[2]), "r"(a[3]), "r"(b[0]), "r"(b[1]));
}

__device__ __forceinline__ void ldsm4(unsigned& r0, unsigned& r1, unsigned& r2,
                                      unsigned& r3, unsigned addr) {
    asm volatile("ldmatrix.sync.aligned.m8n8.x4.shared.b16 {%0,%1,%2,%3}, [%4];"
                 : "=r"(r0), "=r"(r1), "=r"(r2), "=r"(r3) : "r"(addr));
}

__device__ __forceinline__ unsigned su32(const void* p) {
    return (unsigned)__cvta_generic_to_shared(p);
}

__device__ __forceinline__ void cpa16(unsigned dst, const void* src) {
    asm volatile("cp.async.cg.shared.global [%0], [%1], 16;" :: "r"(dst), "l"(src));
}
#define CP_COMMIT() asm volatile("cp.async.commit_group;")
#define CP_WAIT(N)  asm volatile("cp.async.wait_group %0;" :: "n"(N))

// ---------------------------------------------------------------------------
// fp16 conversion passes
// ---------------------------------------------------------------------------
__global__ __launch_bounds__(256) void cvt_x_kernel(const float* __restrict__ src,
                                                    __half* __restrict__ dst)
{
    int i = blockIdx.x * 256 + threadIdx.x;
    float4 v = ((const float4*)src)[i];
    __half2 lo = __floats2half2_rn(v.x, v.y);
    __half2 hi = __floats2half2_rn(v.z, v.w);
    uint2 o;
    o.x = *(unsigned*)&lo; o.y = *(unsigned*)&hi;
    ((uint2*)dst)[i] = o;
}

__global__ __launch_bounds__(256) void cvt_w_kernel(
    const float* __restrict__ w0, const float* __restrict__ w1,
    const float* __restrict__ w2, const float* __restrict__ w3,
    __half* __restrict__ dst)
{
    const float* src = (blockIdx.z == 0) ? w0 : (blockIdx.z == 1) ? w1
                     : (blockIdx.z == 2) ? w2 : w3;
    int i = blockIdx.x * 256 + threadIdx.x;
    float4 v = ((const float4*)src)[i];
    __half2 lo = __floats2half2_rn(v.x, v.y);
    __half2 hi = __floats2half2_rn(v.z, v.w);
    uint2 o;
    o.x = *(unsigned*)&lo; o.y = *(unsigned*)&hi;
    ((uint2*)(dst + (size_t)blockIdx.z * EE * EE))[i] = o;
}

// ---------------------------------------------------------------------------
// fp16 GEMM: block 128x256, BK=32, 256 threads, warp tile 64x64 (2x4 warps),
// 3-stage cp.async pipeline, m16n8k16. Rows padded 32->40 halfs for ldsm.
// PERM: 0 row-major float out; 1 (B,H,S,D) half scaled; 2 (B,H,D,S) half.
// ---------------------------------------------------------------------------
#define GSTAGE 15360                      // halfs per stage (A 128*40 + B 256*40)
#define GSMEM  (3 * GSTAGE * 2)           // 92160 bytes

__device__ __forceinline__ void gemm_issue(unsigned sA, unsigned sB,
                                           const __half* Ap, const __half* Bp)
{
    cpa16(sA, Ap);
    cpa16(sA + 16, Ap + 8);
#pragma unroll
    for (int i = 0; i < 4; i++) cpa16(sB + i * 16, Bp + i * 8);
    CP_COMMIT();
}

template <int PERM>
__device__ __forceinline__ void gemm_body(
    const __half* __restrict__ A, const __half* __restrict__ W,
    const float* __restrict__ bias, void* __restrict__ outv,
    int m0, int n0, float oscale)
{
    extern __shared__ __half smh[];
    const int tid = threadIdx.x;
    const int warp = tid >> 5, lane = tid & 31;
    const int wm = (warp & 1) * 64, wn = (warp >> 1) * 64;
    const int lr = lane >> 2, lc = lane & 3;
    const unsigned g = lane >> 3, r8 = lane & 7;
    const unsigned smb = su32(smh);
    // A-frag lanes: matrices (rows+0-7,k0-7),(rows+8-15,k0-7),(+0-7,k8-15),(+8-15,k8-15)
    const unsigned a_off = ((wm + (g & 1) * 8 + r8) * 40 + (g >> 1) * 8) * 2;
    // B-frag lanes: per x4 covers 2 n-blocks: (n+0-7,k0-7),(n0-7,k8-15),(n8-15,k0-7),(n8-15,k8-15)
    const unsigned b_off = (5120 + (wn + (g >> 1) * 8 + r8) * 40 + (g & 1) * 8) * 2;

    float acc[4][8][4];
#pragma unroll
    for (int i = 0; i < 4; i++)
#pragma unroll
        for (int j = 0; j < 8; j++)
#pragma unroll
            for (int l = 0; l < 4; l++) acc[i][j][l] = 0.f;

    const int ar = tid >> 1;              // 0..127
    const int ac = (tid & 1) * 16;        // halfs
    const __half* Ap = A + (size_t)(m0 + ar) * EE + ac;
    const __half* Bp = W + (size_t)(n0 + tid) * EE;
    const unsigned sA = smb + (ar * 40 + ac) * 2;
    const unsigned sB = smb + (5120 + tid * 40) * 2;

    gemm_issue(sA, sB, Ap, Bp);
    gemm_issue(sA + GSTAGE * 2, sB + GSTAGE * 2, Ap + 32, Bp + 32);

    for (int it = 0; it < 32; it++) {
        CP_WAIT(1);
        __syncthreads();
        if (it + 2 < 32) {
            const int st = (it + 2) % 3;
            gemm_issue(sA + st * GSTAGE * 2, sB + st * GSTAGE * 2,
                       Ap + (it + 2) * 32, Bp + (it + 2) * 32);
        } else {
            CP_COMMIT();
        }
        const unsigned aA = smb + (unsigned)((it % 3) * GSTAGE * 2) + a_off;
        const unsigned aB = smb + (unsigned)((it % 3) * GSTAGE * 2) + b_off;
#pragma unroll
        for (int kk = 0; kk < 2; kk++) {
            unsigned a[4][4], b[8][2];
#pragma unroll
            for (int mt = 0; mt < 4; mt++)
                ldsm4(a[mt][0], a[mt][1], a[mt][2], a[mt][3],
                      aA + (mt * 16 * 40 + kk * 16) * 2);
#pragma unroll
            for (int t = 0; t < 4; t++) {
                unsigned r0, r1, r2, r3;
                ldsm4(r0, r1, r2, r3, aB + (t * 16 * 40 + kk * 16) * 2);
                b[2 * t][0] = r0;     b[2 * t][1] = r1;
                b[2 * t + 1][0] = r2; b[2 * t + 1][1] = r3;
            }
#pragma unroll
            for (int mt = 0; mt < 4; mt++)
#pragma unroll
                for (int nt = 0; nt < 8; nt++)
                    mma16(acc[mt][nt], a[mt], b[nt]);
        }
    }

#pragma unroll
    for (int mt = 0; mt < 4; mt++) {
#pragma unroll
        for (int nt = 0; nt < 8; nt++) {
            int row = m0 + wm + mt * 16 + lr;
            int col = n0 + wn + nt * 8 + lc * 2;
            float bb0 = bias[col], bb1 = bias[col + 1];
            float v00 = acc[mt][nt][0] + bb0, v01 = acc[mt][nt][1] + bb1;
            float v10 = acc[mt][nt][2] + bb0, v11 = acc[mt][nt][3] + bb1;
            if (PERM == 1) {
                __half* out = (__half*)outv;
                int bb = row >> 11, s = row & 2047;
                int h = col >> 6, d = col & 63;
                size_t base = (((size_t)bb * HH + h) * SS + s) * DD + d;
                *(__half2*)(out + base) = __floats2half2_rn(v00 * oscale, v01 * oscale);
                *(__half2*)(out + base + 8 * DD) = __floats2half2_rn(v10 * oscale, v11 * oscale);
            } else if (PERM == 2) {
                __half* out = (__half*)outv;
                int bb = row >> 11, s = row & 2047;
                int h = col >> 6, d = col & 63;
                size_t base = (((size_t)bb * HH + h) * DD + d) * SS + s;
                out[base] = __float2half(v00);
                out[base + SS] = __float2half(v01);
                out[base + 8] = __float2half(v10);
                out[base + SS + 8] = __float2half(v11);
            } else {
                float* out = (float*)outv;
                size_t base = (size_t)row * EE + col;
                out[base] = v00; out[base + 1] = v01;
                out[base + 8 * EE] = v10; out[base + 8 * EE + 1] = v11;
            }
        }
    }
}

__global__ __launch_bounds__(256) void qkv_kernel(
    const __half* __restrict__ x, const __half* __restrict__ w,
    const float* __restrict__ bq, const float* __restrict__ bk,
    const float* __restrict__ bv,
    __half* __restrict__ q, __half* __restrict__ k, __half* __restrict__ v)
{
    const int m0 = blockIdx.y * 128, n0 = blockIdx.x * 256;
    if (blockIdx.z == 0)
        gemm_body<1>(x, w, bq, q, m0, n0, 0.125f * 1.44269504f);
    else if (blockIdx.z == 1)
        gemm_body<1>(x, w + EE * EE, bk, k, m0, n0, 1.f);
    else
        gemm_body<2>(x, w + 2 * EE * EE, bv, v, m0, n0, 1.f);
}

__global__ __launch_bounds__(256) void proj_kernel(
    const __half* __restrict__ A, const __half* __restrict__ W,
    const float* __restrict__ b, float* __restrict__ o)
{
    gemm_body<0>(A, W, b, o, blockIdx.y * 128, blockIdx.x * 256, 1.f);
}

// ---------------------------------------------------------------------------
// fp16 flash attention, causal. Q tile 256 rows (16 warps x 16 rows, 512 thr),
// K/V tile 64 keys, double-buffered, one barrier per tile, m16n8k16.
// Rows padded 64->72 halfs. Smem (halfs):
//   Q/P [0,18432) | K0 [18432) V0 [23040) | K1 [27648) V1 [32256)  total 36864
// ---------------------------------------------------------------------------
#define KOFF 18432
#define VOFF 23040
#define ABUF 18432      // bytes between buffer pairs (9216 halfs)

__global__ __launch_bounds__(512, 1) void attn_kernel(
    const __half* __restrict__ q, const __half* __restrict__ k,
    const __half* __restrict__ vT, __half* __restrict__ o)
{
    extern __shared__ __half smh[];

    const int qt = gridDim.x - 1 - blockIdx.x;   // big tiles first
    const int q0 = qt * 256;
    const int bh = blockIdx.y;
    const int tid = threadIdx.x;
    const int warp = tid >> 5, lane = tid & 31;
    const int lr = lane >> 2, lc = lane & 3;
    const unsigned g = lane >> 3, r8 = lane & 7;
    const unsigned smb = su32(smh);

    const unsigned qf_lane  = smb + ((warp * 16 + (g & 1) * 8 + r8) * 72 + (g >> 1) * 8) * 2;
    const unsigned ks_lane0 = smb + (KOFF + ((g >> 1) * 8 + r8) * 72 + (g & 1) * 8) * 2;
    const unsigned vt_lane0 = smb + (VOFF + ((g >> 1) * 8 + r8) * 72 + (g & 1) * 8) * 2;

    const __half* qb  = q  + (size_t)bh * SS * DD;
    const __half* kb  = k  + (size_t)bh * SS * DD;
    const __half* vTb = vT + (size_t)bh * DD * SS;

    // fill roles: K/V tiles 64 rows x 64 halfs = 512 x 16B chunks, 1 per thread
    const int fr = tid >> 3, fg = tid & 7;
    const __half* kber = kb + (size_t)fr * DD + fg * 8;
    const __half* vber = vTb + (size_t)fr * SS + fg * 8;
    const unsigned kdst = smb + (KOFF + fr * 72 + fg * 8) * 2;
    const unsigned vdst = smb + (VOFF + fr * 72 + fg * 8) * 2;

    // ---- Q tile (256 rows x 64 halfs; 4 chunks per thread) + tile 0 ----
    {
        const int qr = tid & 255, qg = tid >> 8;
        const __half* qsrc = qb + (size_t)(q0 + qr) * DD + qg * 32;
        unsigned qdsm = smb + (qr * 72 + qg * 32) * 2;
#pragma unroll
        for (int p = 0; p < 4; p++) cpa16(qdsm + p * 16, qsrc + p * 8);
        CP_COMMIT();
        cpa16(kdst, kber);
        cpa16(vdst, vber);
        CP_COMMIT();
    }
    CP_WAIT(0);
    __syncthreads();

    // ---- hoist Q fragments via ldsm (own warp slice) ----
    unsigned qf[4][4];
#pragma unroll
    for (int kk = 0; kk < 4; kk++)
        ldsm4(qf[kk][0], qf[kk][1], qf[kk][2], qf[kk][3], qf_lane + kk * 32);

    float m_i0 = -1e30f, m_i1 = -1e30f, l0 = 0.f, l1 = 0.f;
    float oacc[8][4];
#pragma unroll
    for (int i = 0; i < 8; i++)
#pragma unroll
        for (int j = 0; j < 4; j++) oacc[i][j] = 0.f;

    const int row_base = q0 + warp * 16;
    const int ktmax = 4 * qt + 3;

    for (int kt = 0; kt <= ktmax; kt++) {
        __syncthreads();                 // all warps done reading buffer (kt+1)&1
        if (kt < ktmax) {                // prefetch tile kt+1
            const unsigned bn = ((kt + 1) & 1) * ABUF;
            cpa16(kdst + bn, kber + (size_t)(kt + 1) * 64 * DD);
            cpa16(vdst + bn, vber + (kt + 1) * 64);
            CP_COMMIT();
            CP_WAIT(1);                  // tile kt complete
        } else {
            CP_WAIT(0);
        }

        if (kt * 64 > row_base + 15) continue;   // fully masked for this warp

        const unsigned bo = (kt & 1) * ABUF;
        const unsigned ks_lane = ks_lane0 + bo;
        const unsigned vt_lane = vt_lane0 + bo;

        // ---- S = Q K^T (16 x 64) ----
        float sacc[8][4];
#pragma unroll
        for (int i = 0; i < 8; i++)
#pragma unroll
            for (int j = 0; j < 4; j++) sacc[i][j] = 0.f;
#pragma unroll
        for (int kk = 0; kk < 4; kk++) {
#pragma unroll
            for (int t = 0; t < 4; t++) {
                unsigned b0, b1, b2, b3;
                ldsm4(b0, b1, b2, b3, ks_lane + (t * 16 * 72 + kk * 16) * 2);
                unsigned bb0[2] = { b0, b1 }, bb1[2] = { b2, b3 };
                mma16(sacc[2 * t], qf[kk], bb0);
                mma16(sacc[2 * t + 1], qf[kk], bb1);
            }
        }

        // ---- causal mask (log2-domain scores) ----
        if (kt * 64 + 63 > row_base) {
            const int row0 = row_base + lr;
#pragma unroll
            for (int nt = 0; nt < 8; nt++) {
                int c0 = kt * 64 + nt * 8 + lc * 2;
                if (c0     > row0)     sacc[nt][0] = -1e30f;
                if (c0 + 1 > row0)     sacc[nt][1] = -1e30f;
                if (c0     > row0 + 8) sacc[nt][2] = -1e30f;
                if (c0 + 1 > row0 + 8) sacc[nt][3] = -1e30f;
            }
        }

        // ---- online softmax (ex2.approx) ----
        float mx0 = -1e30f, mx1 = -1e30f;
#pragma unroll
        for (int nt = 0; nt < 8; nt++) {
            mx0 = fmaxf(mx0, fmaxf(sacc[nt][0], sacc[nt][1]));
            mx1 = fmaxf(mx1, fmaxf(sacc[nt][2], sacc[nt][3]));
        }
        mx0 = fmaxf(mx0, __shfl_xor_sync(0xffffffffu, mx0, 1));
        mx1 = fmaxf(mx1, __shfl_xor_sync(0xffffffffu, mx1, 1));
        mx0 = fmaxf(mx0, __shfl_xor_sync(0xffffffffu, mx0, 2));
        mx1 = fmaxf(mx1, __shfl_xor_sync(0xffffffffu, mx1, 2));

        float mn0 = fmaxf(m_i0, mx0), mn1 = fmaxf(m_i1, mx1);
        float corr0 = fexp2(m_i0 - mn0), corr1 = fexp2(m_i1 - mn1);
        m_i0 = mn0; m_i1 = mn1;

        float sum0 = 0.f, sum1 = 0.f;
#pragma unroll
        for (int nt = 0; nt < 8; nt++) {
            sacc[nt][0] = fexp2(sacc[nt][0] - mn0);
            sacc[nt][1] = fexp2(sacc[nt][1] - mn0);
            sacc[nt][2] = fexp2(sacc[nt][2] - mn1);
            sacc[nt][3] = fexp2(sacc[nt][3] - mn1);
            sum0 += sacc[nt][0] + sacc[nt][1];
            sum1 += sacc[nt][2] + sacc[nt][3];
        }
        sum0 += __shfl_xor_sync(0xffffffffu, sum0, 1);
        sum1 += __shfl_xor_sync(0xffffffffu, sum1, 1);
        sum0 += __shfl_xor_sync(0xffffffffu, sum0, 2);
        sum1 += __shfl_xor_sync(0xffffffffu, sum1, 2);
        l0 = l0 * corr0 + sum0;
        l1 = l1 * corr1 + sum1;

#pragma unroll
        for (int dt = 0; dt < 8; dt++) {
            oacc[dt][0] *= corr0; oacc[dt][1] *= corr0;
            oacc[dt][2] *= corr1; oacc[dt][3] *= corr1;
        }

        // ---- spill P (fp16 pairs) to this warp's Q-region slice ----
        __half2* Pw = (__half2*)(smh + (size_t)warp * 16 * 72);
        __syncwarp();
#pragma unroll
        for (int nt = 0; nt < 8; nt++) {
            Pw[lr * 36 + nt * 4 + lc]       = __floats2half2_rn(sacc[nt][0], sacc[nt][1]);
            Pw[(lr + 8) * 36 + nt * 4 + lc] = __floats2half2_rn(sacc[nt][2], sacc[nt][3]);
        }
        __syncwarp();

        // ---- O += P @ V ----
#pragma unroll
        for (int kk = 0; kk < 4; kk++) {
            unsigned pa[4];
            ldsm4(pa[0], pa[1], pa[2], pa[3], qf_lane + kk * 32);
#pragma unroll
            for (int t = 0; t < 4; t++) {
                unsigned b0, b1, b2, b3;
                ldsm4(b0, b1, b2, b3, vt_lane + (t * 16 * 72 + kk * 16) * 2);
                unsigned bb0[2] = { b0, b1 }, bb1[2] = { b2, b3 };
                mma16(oacc[2 * t], pa, bb0);
                mma16(oacc[2 * t + 1], pa, bb1);
            }
        }
    }

    // ---- epilogue: normalize, write (B, S, E) as fp16 for proj ----
    float inv0 = 1.f / l0, inv1 = 1.f / l1;
    int bb = bh >> 4, h = bh & 15;
    int s0 = q0 + warp * 16 + lr;
#pragma unroll
    for (int dt = 0; dt < 8; dt++) {
        int d = dt * 8 + lc * 2;
        size_t i0 = ((size_t)bb * SS + s0) * EE + h * 64 + d;
        *(__half2*)(o + i0) = __floats2half2_rn(oacc[dt][0] * inv0, oacc[dt][1] * inv0);
        size_t i1 = i0 + (size_t)8 * EE;
        *(__half2*)(o + i1) = __floats2half2_rn(oacc[dt][2] * inv1, oacc[dt][3] * inv1);
    }
}

// ---------------------------------------------------------------------------
extern "C" void kernel_launch(void* const* d_in, const int* in_sizes, int n_in,
                              void* d_out, int out_size)
{
    const float* x  = (const float*)d_in[0];
    const float* Wq = (const float*)d_in[1];
    const float* bq = (const float*)d_in[2];
    const float* Wk = (const float*)d_in[3];
    const float* bk = (const float*)d_in[4];
    const float* Wv = (const float*)d_in[5];
    const float* bv = (const float*)d_in[6];
    const float* Wo = (const float*)d_in[7];
    const float* bo = (const float*)d_in[8];

    void *pq, *pk, *pv, *pa, *px, *pw;
    cudaGetSymbolAddress(&pq, g_q);
    cudaGetSymbolAddress(&pk, g_k);
    cudaGetSymbolAddress(&pv, g_v);
    cudaGetSymbolAddress(&pa, g_att);
    cudaGetSymbolAddress(&px, g_x);
    cudaGetSymbolAddress(&pw, g_w);
    __half* fx = (__half*)px;
    __half* fw = (__half*)pw;

    const int attn_smem = 36864 * 2;   // 73728 bytes
    cudaFuncSetAttribute(qkv_kernel, cudaFuncAttributeMaxDynamicSharedMemorySize, GSMEM);
    cudaFuncSetAttribute(proj_kernel, cudaFuncAttributeMaxDynamicSharedMemorySize, GSMEM);
    cudaFuncSetAttribute(attn_kernel, cudaFuncAttributeMaxDynamicSharedMemorySize, attn_smem);

    cvt_x_kernel<<<MM * EE / 4 / 256, 256>>>(x, fx);
    cvt_w_kernel<<<dim3(EE * EE / 4 / 256, 1, 4), 256>>>(Wq, Wk, Wv, Wo, fw);

    qkv_kernel<<<dim3(EE / 256, MM / 128, 3), 256, GSMEM>>>(
        fx, fw, bq, bk, bv, (__half*)pq, (__half*)pk, (__half*)pv);

    attn_kernel<<<dim3(SS / 256, 2 * HH), 512, attn_smem>>>(
        (const __half*)pq, (const __half*)pk, (const __half*)pv, (__half*)pa);

    proj_kernel<<<dim3(EE / 256, MM / 128), 256, GSMEM>>>(
        (const __half*)pa, fw + 3 * EE * EE, bo, (float*)d_out);
}